// round 11
// baseline (speedup 1.0000x reference)
#include <cuda_runtime.h>
#include <math.h>

// Problem constants (fixed by reference setup_inputs)
#define NB 32
#define BV 516
#define NS 2048
#define NROWS (NB * BV)     // 16512
#define NCOLS (NB * NS)     // 65536
#define TPB 256
#define NPROD 4128          // 4-row producer blocks (516/4 * 32)
#define NCONS 512           // consumers: 16 per batch (4 s-chunks x 4 v-chunks)
#define NGRID (NPROD + NCONS)   // 4640
#define NVCHUNK 4
#define VCHUNK 129
#define SCW 512             // consumer columns per block (2 per thread)
#define TPBC 128
#define NBLKC (NCOLS / TPBC)    // 512 comb blocks
#define NEG_BIG (-1e30f)

// Scratch (no allocations allowed -> __device__ globals; zero-initialized)
__device__ float    g_lse[NROWS];
__device__ unsigned g_done[NB];          // producers finished per batch
__device__ __align__(16) float g_psum [NVCHUNK * NCOLS];
__device__ __align__(16) float g_pbest[NVCHUNK * NCOLS];
__device__ __align__(16) int   g_pbi  [NVCHUNK * NCOLS];
__device__ double   g_part_nll[NBLKC];
__device__ double   g_part_mask[NBLKC];
__device__ unsigned g_arrive;

// ---------------------------------------------------------------------------
// Fused kernel, static role assignment: bid%9==8 (and jc<512) -> consumer,
// else producer. Consumers interleave with the producers of their own batch
// in dispatch order -> overlap DRAM streaming (producers) with L2-hot
// column passes (consumers). Deadlock-free by capacity: 512 consumers <
// 1184 resident block slots, so producers always have SM slots.
// ---------------------------------------------------------------------------
__global__ void __launch_bounds__(TPB) k_fused(const float* __restrict__ out) {
    const int bid = blockIdx.x;
    const int jc  = bid / 9;
    const bool is_cons = ((bid % 9) == 8) && (jc < NCONS);
    const int tid = threadIdx.x;

    if (!is_cons) {
        // ============ producer: LSE of 4 rows (proven body) ============
        const int prank = bid - (jc < NCONS ? jc : NCONS);
        const int b     = prank / 129;              // 129 producers per batch
        const int r0    = prank * 4;                // global row base
        const float4* p = reinterpret_cast<const float4*>(out) + (size_t)r0 * (NS / 4);

        float4 x[8];
        #pragma unroll
        for (int k = 0; k < 4; k++) {
            x[2 * k]     = __ldg(p + k * 512 + tid);
            x[2 * k + 1] = __ldg(p + k * 512 + 256 + tid);
        }
        float s[4];
        #pragma unroll
        for (int k = 0; k < 4; k++) {
            float4 a = x[2 * k], bq = x[2 * k + 1];
            s[k] = __expf(a.x) + __expf(a.y) + __expf(a.z) + __expf(a.w)
                 + __expf(bq.x) + __expf(bq.y) + __expf(bq.z) + __expf(bq.w);
        }
        #pragma unroll
        for (int o = 16; o; o >>= 1) {
            #pragma unroll
            for (int k = 0; k < 4; k++)
                s[k] += __shfl_down_sync(0xffffffffu, s[k], o);
        }
        __shared__ float sh[4][8];
        if ((tid & 31) == 0) {
            #pragma unroll
            for (int k = 0; k < 4; k++) sh[k][tid >> 5] = s[k];
        }
        __syncthreads();
        if (tid < 8) {
            float v0 = sh[0][tid], v1 = sh[1][tid], v2 = sh[2][tid], v3 = sh[3][tid];
            #pragma unroll
            for (int o = 4; o; o >>= 1) {
                v0 += __shfl_down_sync(0xffu, v0, o);
                v1 += __shfl_down_sync(0xffu, v1, o);
                v2 += __shfl_down_sync(0xffu, v2, o);
                v3 += __shfl_down_sync(0xffu, v3, o);
            }
            if (tid == 0) {
                g_lse[r0]     = __logf(v0);
                g_lse[r0 + 1] = __logf(v1);
                g_lse[r0 + 2] = __logf(v2);
                g_lse[r0 + 3] = __logf(v3);
                __threadfence();
                atomicAdd(&g_done[b], 1u);
            }
        }
    } else {
        // ============ consumer: 129 rows x 512 cols column pass ============
        const int j  = jc;
        const int b  = j >> 4;            // batch
        const int sc = (j >> 2) & 3;      // s-chunk of 512 cols
        const int c  = j & 3;             // v-chunk of 129 rows
        const int v0 = c * VCHUNK;
        const int s0 = sc * SCW + 2 * tid;

        if (tid == 0) {
            volatile unsigned* dp = g_done + b;
            while (*dp < 129u) { __nanosleep(100); }
        }
        __syncthreads();
        __threadfence();   // order subsequent loads after the flag read

        __shared__ float sh_lse[VCHUNK];
        for (int i = tid; i < VCHUNK; i += TPB)
            sh_lse[i] = g_lse[b * BV + v0 + i];
        __syncthreads();

        const float* col = out + ((size_t)b * BV + v0) * NS + s0;

        float sum0 = 0.f, sum1 = 0.f;
        float best0 = NEG_BIG, best1 = NEG_BIG;
        int   bi0 = 0, bi1 = 0;

        int v = 0;
        #pragma unroll 1
        for (; v < 128; v += 8) {
            float2 x[8];
            #pragma unroll
            for (int r = 0; r < 8; r++)
                x[r] = __ldg(reinterpret_cast<const float2*>(col + (size_t)(v + r) * NS));
            #pragma unroll
            for (int r = 0; r < 8; r++) {
                sum0 += __expf(x[r].x);
                sum1 += __expf(x[r].y);
                const float l = sh_lse[v + r];
                const float a0 = x[r].x - l, a1 = x[r].y - l;
                if (a0 > best0) { best0 = a0; bi0 = v + r; }
                if (a1 > best1) { best1 = a1; bi1 = v + r; }
            }
        }
        {   // remainder row 128
            const float2 xv = __ldg(reinterpret_cast<const float2*>(col + (size_t)128 * NS));
            sum0 += __expf(xv.x);
            sum1 += __expf(xv.y);
            const float l = sh_lse[128];
            const float a0 = xv.x - l, a1 = xv.y - l;
            if (a0 > best0) { best0 = a0; bi0 = 128; }
            if (a1 > best1) { best1 = a1; bi1 = 128; }
        }

        const int n = b * NS + s0;   // 8B-aligned (s0 even)
        *reinterpret_cast<float2*>(g_psum  + c * NCOLS + n) = make_float2(sum0, sum1);
        *reinterpret_cast<float2*>(g_pbest + c * NCOLS + n) = make_float2(best0, best1);
        *reinterpret_cast<int2*>  (g_pbi   + c * NCOLS + n) = make_int2(v0 + bi0, v0 + bi1);
    }
}

// ---------------------------------------------------------------------------
// Combine: per column merge 4 chunk partials (fixed order -> exact first-max
// argmax), nll + penalty mask, deterministic reduction, fused finalize,
// and counter reset for the next graph replay.
// ---------------------------------------------------------------------------
__global__ void __launch_bounds__(TPBC) k_comb(
    const float* __restrict__ out,
    const int*   __restrict__ target,
    const int*   __restrict__ ttype,
    const float* __restrict__ tvalue,
    const float* __restrict__ coeff,
    const float* __restrict__ harm,
    float*       __restrict__ res)
{
    const int n = blockIdx.x * TPBC + threadIdx.x;   // 0..65535
    const int b = n >> 11;
    const int s = n & (NS - 1);

    float sum = 0.0f, best = NEG_BIG;
    int bi = 0;
    #pragma unroll
    for (int c = 0; c < NVCHUNK; c++) {
        sum += g_psum[c * NCOLS + n];
        const float bb = g_pbest[c * NCOLS + n];
        if (bb > best) { best = bb; bi = g_pbi[c * NCOLS + n]; }
    }

    const int tgt = target[n];
    const float t_logit = __ldg(out + ((size_t)b * BV + tgt) * NS + s);
    const float nll = __logf(sum) - t_logit;

    // penalty mask
    const int   pt = __ldg(ttype  + bi), qt = __ldg(ttype  + tgt);
    const float pv = __ldg(tvalue + bi), qv = __ldg(tvalue + tgt);
    const float d  = fabsf(pv - qv);

    float pw = (d == 7.0f) ? __ldg(harm + 0)
             : (d == 5.0f) ? __ldg(harm + 1)
             : (d == 3.0f) ? __ldg(harm + 2)
             : (d == 4.0f) ? __ldg(harm + 3)
             : (d == 1.0f) ? __ldg(harm + 4)
             : (d == 2.0f) ? __ldg(harm + 5)
             :               __ldg(harm + 6);

    float w;
    if (pt != qt)       w = __ldg(coeff + 0);
    else if (pt == 0)   w = pw;
    else if (pt == 1)   w = __ldg(coeff + 1) * d * (1.0f / 160.0f);
    else if (pt == 2)   w = __ldg(coeff + 2) * d * (1.0f / 100.0f);
    else                w = __ldg(coeff + 3) * d * (1.0f / 128.0f);

    // block reduction (double), fixed order
    double dn = (double)nll, dm = (double)w;
    #pragma unroll
    for (int o = 16; o; o >>= 1) {
        dn += __shfl_down_sync(0xffffffffu, dn, o);
        dm += __shfl_down_sync(0xffffffffu, dm, o);
    }
    __shared__ double shn[TPBC / 32], shm[TPBC / 32];
    const int wid = threadIdx.x >> 5;
    if ((threadIdx.x & 31) == 0) { shn[wid] = dn; shm[wid] = dm; }
    __syncthreads();

    __shared__ bool s_last;
    if (threadIdx.x == 0) {
        double an = 0.0, am = 0.0;
        #pragma unroll
        for (int i = 0; i < TPBC / 32; i++) { an += shn[i]; am += shm[i]; }
        g_part_nll[blockIdx.x]  = an;
        g_part_mask[blockIdx.x] = am;
        __threadfence();
        unsigned prev = atomicAdd(&g_arrive, 1u);
        s_last = (prev == NBLKC - 1);
    }
    __syncthreads();

    if (s_last) {
        const int t = threadIdx.x;
        double an = 0.0, am = 0.0;
        #pragma unroll
        for (int k = 0; k < NBLKC / TPBC; k++) {
            an += g_part_nll[t + k * TPBC];
            am += g_part_mask[t + k * TPBC];
        }
        #pragma unroll
        for (int o = 16; o; o >>= 1) {
            an += __shfl_down_sync(0xffffffffu, an, o);
            am += __shfl_down_sync(0xffffffffu, am, o);
        }
        if ((t & 31) == 0) { shn[t >> 5] = an; shm[t >> 5] = am; }
        __syncthreads();
        // reset per-replay counters (graph replays reuse device globals)
        if (t < NB) g_done[t] = 0u;
        if (t == 0) {
            double fn = 0.0, fm = 0.0;
            #pragma unroll
            for (int i = 0; i < TPBC / 32; i++) { fn += shn[i]; fm += shm[i]; }
            const double inv = 1.0 / (double)NCOLS;
            const double loss = fn * inv;
            res[0] = (float)(loss * (1.0 + fm * inv));
            g_arrive = 0u;
        }
    }
}

extern "C" void kernel_launch(void* const* d_in, const int* in_sizes, int n_in,
                              void* d_out, int out_size)
{
    const float* output  = (const float*)d_in[0];   // [32, 516, 2048] f32
    const int*   target  = (const int*)  d_in[1];   // [32, 2048] i32
    const int*   ttype   = (const int*)  d_in[2];   // [516] i32
    const float* tvalue  = (const float*)d_in[3];   // [516] f32
    const float* coeff   = (const float*)d_in[4];   // [4] f32
    const float* harm    = (const float*)d_in[5];   // [7] f32
    float* out = (float*)d_out;

    k_fused<<<NGRID, TPB>>>(output);
    k_comb<<<NBLKC, TPBC>>>(output, target, ttype, tvalue, coeff, harm, out);
}

// round 12
// speedup vs baseline: 1.3750x; 1.3750x over previous
#include <cuda_runtime.h>
#include <math.h>

// Problem constants (fixed by reference setup_inputs)
#define NB 32
#define BV 516
#define NS 2048
#define NROWS (NB * BV)     // 16512
#define NCOLS (NB * NS)     // 65536
#define TPB2 128
#define NVCHUNK 4
#define VCHUNK 129          // 516 / 4
#define TPBC 256
#define NBLKC (NCOLS / TPBC)   // 256 comb blocks
#define NEG_BIG (-1e30f)

// Scratch (no allocations allowed -> __device__ globals; zero-initialized)
__device__ float  g_lse[NROWS];
__device__ float  g_psum [NVCHUNK * NCOLS];
__device__ float  g_pbest[NVCHUNK * NCOLS];
__device__ int    g_pbi  [NVCHUNK * NCOLS];
__device__ float  g_tlogit[NCOLS];
__device__ double g_part_nll[NBLKC];
__device__ double g_part_mask[NBLKC];
__device__ unsigned g_arrive;   // reset by last comb block each replay

// ---------------------------------------------------------------------------
// Kernel 1 (proven 24.7us): per-(b,v) row log-sum-exp over the seq axis.
// One block per FOUR rows, 256 threads, 8 front-batched float4 loads/thread.
// ---------------------------------------------------------------------------
__global__ void __launch_bounds__(256) k_lse_seq(const float* __restrict__ out) {
    const int bp = blockIdx.x;                        // group of 4 rows
    const float4* p = reinterpret_cast<const float4*>(out) + (size_t)bp * 2048;
    const int t = threadIdx.x;

    float4 x[8];
    #pragma unroll
    for (int k = 0; k < 4; k++) {
        x[2 * k]     = __ldg(p + k * 512 + t);
        x[2 * k + 1] = __ldg(p + k * 512 + 256 + t);
    }
    float s[4];
    #pragma unroll
    for (int k = 0; k < 4; k++) {
        float4 a = x[2 * k], b = x[2 * k + 1];
        s[k] = __expf(a.x) + __expf(a.y) + __expf(a.z) + __expf(a.w)
             + __expf(b.x) + __expf(b.y) + __expf(b.z) + __expf(b.w);
    }
    #pragma unroll
    for (int o = 16; o; o >>= 1) {
        #pragma unroll
        for (int k = 0; k < 4; k++)
            s[k] += __shfl_down_sync(0xffffffffu, s[k], o);
    }
    __shared__ float sh[4][8];
    if ((t & 31) == 0) {
        #pragma unroll
        for (int k = 0; k < 4; k++) sh[k][t >> 5] = s[k];
    }
    __syncthreads();
    if (t < 8) {
        float v0 = sh[0][t], v1 = sh[1][t], v2 = sh[2][t], v3 = sh[3][t];
        #pragma unroll
        for (int o = 4; o; o >>= 1) {
            v0 += __shfl_down_sync(0xffu, v0, o);
            v1 += __shfl_down_sync(0xffu, v1, o);
            v2 += __shfl_down_sync(0xffu, v2, o);
            v3 += __shfl_down_sync(0xffu, v3, o);
        }
        if (t == 0) {
            g_lse[4 * bp]     = __logf(v0);
            g_lse[4 * bp + 1] = __logf(v1);
            g_lse[4 * bp + 2] = __logf(v2);
            g_lse[4 * bp + 3] = __logf(v3);
        }
    }
}

// ---------------------------------------------------------------------------
// Kernel 2 (proven main loop): partial column pass per (s-chunk, b, v-chunk).
// NEW: the chunk containing target[n] also captures o[tgt,s] (L1/L2-hot,
// the block just streamed that row) -> k_comb needs no cold scattered gather.
// ---------------------------------------------------------------------------
__global__ void __launch_bounds__(TPB2) k_col_part(const float* __restrict__ out,
                                                   const int* __restrict__ target) {
    const int b  = blockIdx.y;
    const int c  = blockIdx.z;
    const int s  = blockIdx.x * TPB2 + threadIdx.x;
    const int v0 = c * VCHUNK;

    __shared__ float sh_lse[VCHUNK];
    for (int i = threadIdx.x; i < VCHUNK; i += TPB2)
        sh_lse[i] = g_lse[b * BV + v0 + i];
    __syncthreads();

    const float* col = out + (size_t)b * BV * NS + (size_t)v0 * NS + s;

    float sum  = 0.0f;
    float best = NEG_BIG;
    int   bi   = 0;

    int v = 0;
    #pragma unroll 1
    for (; v < 128; v += 16) {
        float x[16];
        #pragma unroll
        for (int j = 0; j < 16; j++)
            x[j] = __ldg(col + (size_t)(v + j) * NS);
        #pragma unroll
        for (int j = 0; j < 16; j++) {
            sum += __expf(x[j]);
            float sc = x[j] - sh_lse[v + j];
            if (sc > best) { best = sc; bi = v + j; }
        }
    }
    {   // remainder: v = 128 (129th entry)
        float xv = __ldg(col + (size_t)128 * NS);
        sum += __expf(xv);
        float sc = xv - sh_lse[128];
        if (sc > best) { best = sc; bi = 128; }
    }

    const int n = b * NS + s;
    g_psum [c * NCOLS + n] = sum;
    g_pbest[c * NCOLS + n] = best;
    g_pbi  [c * NCOLS + n] = v0 + bi;

    // hot target-logit capture: exactly one chunk owns tgt
    const int tgt = __ldg(target + n);
    const int tl  = tgt - v0;
    if ((unsigned)tl < (unsigned)VCHUNK)
        g_tlogit[n] = __ldg(col + (size_t)tl * NS);
}

// ---------------------------------------------------------------------------
// Kernel 3: streaming-only combine (no scattered gathers). Merge 4 chunk
// partials per column (fixed order -> exact first-max argmax), nll + penalty
// mask, deterministic reduction, fused last-block finalize + counter reset.
// ---------------------------------------------------------------------------
__global__ void __launch_bounds__(TPBC) k_comb(
    const int*   __restrict__ target,
    const int*   __restrict__ ttype,
    const float* __restrict__ tvalue,
    const float* __restrict__ coeff,
    const float* __restrict__ harm,
    float*       __restrict__ res)
{
    const int n = blockIdx.x * TPBC + threadIdx.x;   // 0..65535

    float sum = 0.0f, best = NEG_BIG;
    int bi = 0;
    #pragma unroll
    for (int c = 0; c < NVCHUNK; c++) {
        sum += g_psum[c * NCOLS + n];
        const float bb = g_pbest[c * NCOLS + n];
        if (bb > best) { best = bb; bi = g_pbi[c * NCOLS + n]; }
    }

    const int tgt = __ldg(target + n);
    const float nll = __logf(sum) - g_tlogit[n];

    // penalty mask
    const int   pt = __ldg(ttype  + bi), qt = __ldg(ttype  + tgt);
    const float pv = __ldg(tvalue + bi), qv = __ldg(tvalue + tgt);
    const float d  = fabsf(pv - qv);

    float pw = (d == 7.0f) ? __ldg(harm + 0)
             : (d == 5.0f) ? __ldg(harm + 1)
             : (d == 3.0f) ? __ldg(harm + 2)
             : (d == 4.0f) ? __ldg(harm + 3)
             : (d == 1.0f) ? __ldg(harm + 4)
             : (d == 2.0f) ? __ldg(harm + 5)
             :               __ldg(harm + 6);

    float w;
    if (pt != qt)       w = __ldg(coeff + 0);
    else if (pt == 0)   w = pw;
    else if (pt == 1)   w = __ldg(coeff + 1) * d * (1.0f / 160.0f);
    else if (pt == 2)   w = __ldg(coeff + 2) * d * (1.0f / 100.0f);
    else                w = __ldg(coeff + 3) * d * (1.0f / 128.0f);

    // block reduction (double), fixed order
    double dn = (double)nll, dm = (double)w;
    #pragma unroll
    for (int o = 16; o; o >>= 1) {
        dn += __shfl_down_sync(0xffffffffu, dn, o);
        dm += __shfl_down_sync(0xffffffffu, dm, o);
    }
    __shared__ double shn[TPBC / 32], shm[TPBC / 32];
    const int wid = threadIdx.x >> 5;
    if ((threadIdx.x & 31) == 0) { shn[wid] = dn; shm[wid] = dm; }
    __syncthreads();

    __shared__ bool s_last;
    if (threadIdx.x == 0) {
        double an = 0.0, am = 0.0;
        #pragma unroll
        for (int i = 0; i < TPBC / 32; i++) { an += shn[i]; am += shm[i]; }
        g_part_nll[blockIdx.x]  = an;
        g_part_mask[blockIdx.x] = am;
        __threadfence();
        unsigned prev = atomicAdd(&g_arrive, 1u);
        s_last = (prev == NBLKC - 1);
    }
    __syncthreads();

    if (s_last) {
        const int t = threadIdx.x;
        double an = g_part_nll[t];     // NBLKC == TPBC: one slot per thread
        double am = g_part_mask[t];
        #pragma unroll
        for (int o = 16; o; o >>= 1) {
            an += __shfl_down_sync(0xffffffffu, an, o);
            am += __shfl_down_sync(0xffffffffu, am, o);
        }
        if ((t & 31) == 0) { shn[t >> 5] = an; shm[t >> 5] = am; }
        __syncthreads();
        if (t == 0) {
            double fn = 0.0, fm = 0.0;
            #pragma unroll
            for (int i = 0; i < TPBC / 32; i++) { fn += shn[i]; fm += shm[i]; }
            const double inv = 1.0 / (double)NCOLS;
            const double loss = fn * inv;
            res[0] = (float)(loss * (1.0 + fm * inv));
            g_arrive = 0u;   // reset for next graph replay
        }
    }
}

extern "C" void kernel_launch(void* const* d_in, const int* in_sizes, int n_in,
                              void* d_out, int out_size)
{
    const float* output  = (const float*)d_in[0];   // [32, 516, 2048] f32
    const int*   target  = (const int*)  d_in[1];   // [32, 2048] i32
    const int*   ttype   = (const int*)  d_in[2];   // [516] i32
    const float* tvalue  = (const float*)d_in[3];   // [516] f32
    const float* coeff   = (const float*)d_in[4];   // [4] f32
    const float* harm    = (const float*)d_in[5];   // [7] f32
    float* out = (float*)d_out;

    k_lse_seq<<<NROWS / 4, 256>>>(output);
    k_col_part<<<dim3(NS / TPB2, NB, NVCHUNK), TPB2>>>(output, target);
    k_comb<<<NBLKC, TPBC>>>(target, ttype, tvalue, coeff, harm, out);
}